// round 8
// baseline (speedup 1.0000x reference)
#include <cuda_runtime.h>
#include <cuda_fp16.h>
#include <math.h>
#include <stdint.h>

#define DN    512
#define DQv   256
#define NPG   4096
#define NB    64
#define MI    8
#define NTOT  (NB*NPG)
#define KSEL  1229           // ceil(0.3 * 4096)

// ---- HMMA tiles
#define BM   128
#define BN   128
#define BK   32
#define NSTG (DN/BK)         // 16

// ---- FFMA tiles
#define FBM  64
#define FBK  8
#define FNKT (DN/FBK)        // 64

// ---- split: H covers rows [0, HROWS), F the rest
#define HSLABS 1382
#define HROWS  (HSLABS*128)            // 176896
#define FBLKS  ((NTOT-HROWS)/FBM)      // 1332

// ---------------- scratch ----------------
__device__ float g_s0[NB * MI * NPG];     // scores partial (H col-half 0 / F full)
__device__ float g_s1[NB * MI * NPG];     // H col-half 1 (F rows: zero)
__device__ __half g_Whi[DN * DQv];        // W*512 split hi
__device__ __half g_Wlo[DN * DQv];        // W*512 split lo

// ---------------- HMMA smem layout (bytes) ----------------
#define A_PAD 40
#define B_PAD 136
#define SM_AHI 0
#define SM_ALO 20480
#define SM_BHI 40960
#define SM_BLO 58368
#define SM_US  75776
#define SM_BNv 79872
#define SM_DYN 80384
#define A_STG  10240
#define B_STG  8704

__device__ __forceinline__ uint32_t smem_u32(const void* p) {
    uint32_t a;
    asm("{ .reg .u64 t; cvta.to.shared.u64 t, %1; cvt.u32.u64 %0, t; }"
        : "=r"(a) : "l"(p));
    return a;
}

#define LDSM4(r, addr) \
    asm volatile("ldmatrix.sync.aligned.m8n8.x4.shared.b16 {%0,%1,%2,%3}, [%4];" \
        : "=r"((r)[0]), "=r"((r)[1]), "=r"((r)[2]), "=r"((r)[3]) : "r"(addr))

#define LDSM4T(r, addr) \
    asm volatile("ldmatrix.sync.aligned.m8n8.x4.trans.shared.b16 {%0,%1,%2,%3}, [%4];" \
        : "=r"((r)[0]), "=r"((r)[1]), "=r"((r)[2]), "=r"((r)[3]) : "r"(addr))

#define MMA16816(c, a, b0, b1) \
    asm volatile("mma.sync.aligned.m16n8k16.row.col.f32.f16.f16.f32 " \
        "{%0,%1,%2,%3}, {%4,%5,%6,%7}, {%8,%9}, {%0,%1,%2,%3};" \
        : "+f"((c)[0]), "+f"((c)[1]), "+f"((c)[2]), "+f"((c)[3]) \
        : "r"((a)[0]), "r"((a)[1]), "r"((a)[2]), "r"((a)[3]), "r"(b0), "r"(b1))

__device__ __forceinline__ unsigned long long fma2(unsigned long long a,
                                                   unsigned long long b,
                                                   unsigned long long c) {
    unsigned long long d;
    asm("fma.rn.f32x2 %0, %1, %2, %3;" : "=l"(d) : "l"(a), "l"(b), "l"(c));
    return d;
}

// ---------------------------------------------------------------------------
// Prologue: W [512][256] fp32 -> fp16 Dekker split of W*512
// ---------------------------------------------------------------------------
__global__ void convert_w(const float* __restrict__ Wn) {
    int idx = blockIdx.x * 256 + threadIdx.x;
    float w = Wn[idx] * 512.0f;
    __half hi = __float2half_rn(w);
    __half lo = __float2half_rn(w - __half2float(hi));
    g_Whi[idx] = hi;
    g_Wlo[idx] = lo;
}

// ---------------------------------------------------------------------------
// HMMA kernel (round-5 design): 128 rows x 128 cols, fp16 2-split 3-term.
// grid = (HSLABS, 2). Own register budget: 152 regs.
// ---------------------------------------------------------------------------
__global__ void __maxnreg__(152)
gemm_hmma(const float* __restrict__ x, const float* __restrict__ u,
          const float* __restrict__ bn)
{
    extern __shared__ char smem[];
    const uint32_t sb = smem_u32(smem);
    const int tid  = threadIdx.x;
    const int wid  = tid >> 5, lane = tid & 31;
    const int wm   = wid & 3, wn = wid >> 2;
    const int rowBase = blockIdx.x * BM;
    const int colBase = blockIdx.y * BN;
    const int b = rowBase >> 12;
    float* gs = blockIdx.y ? g_s1 : g_s0;

    float* UsS = (float*)(smem + SM_US);
    float* bnS = (float*)(smem + SM_BNv);
    for (int i = tid; i < MI * BN; i += 256) {
        int m = i >> 7, c = i & 127;
        UsS[i] = u[(m * NB + b) * DQv + colBase + c];
    }
    if (tid < BN) bnS[tid] = bn[colBase + tid];

    const int arow = tid >> 1;
    const int ac0  = (tid & 1) * 16;
    const float* Ap = x + (size_t)(rowBase + arow) * DN + ac0;
    const int aoff  = (arow * A_PAD + ac0) * 2;

    const int brow = tid >> 3;
    const int bc0  = (tid & 7) * 16;
    const __half* WHp = g_Whi + (size_t)brow * DQv + colBase + bc0;
    const __half* WLp = g_Wlo + (size_t)brow * DQv + colBase + bc0;
    const int boff  = (brow * B_PAD + bc0) * 2;

    const uint32_t aHiB = sb + SM_AHI, aLoB = sb + SM_ALO;
    const uint32_t bHiB = sb + SM_BHI, bLoB = sb + SM_BLO;
    const uint32_t arow_l = ((wm * 32 + (lane & 15)) * A_PAD + (lane >> 4) * 8) * 2;
    const uint32_t brow_l = ((lane & 15) * B_PAD + wn * 64 + (lane >> 4) * 8) * 2;

    float acc[2][8][4];
    #pragma unroll
    for (int mt = 0; mt < 2; ++mt)
        #pragma unroll
        for (int nt = 0; nt < 8; ++nt)
            #pragma unroll
            for (int i = 0; i < 4; ++i) acc[mt][nt][i] = 0.f;

    float4 fA[4];
    uint4  gB[4];

    {
        const float4* p = (const float4*)Ap;
        fA[0] = p[0]; fA[1] = p[1]; fA[2] = p[2]; fA[3] = p[3];
        gB[0] = ((const uint4*)WHp)[0]; gB[1] = ((const uint4*)WHp)[1];
        gB[2] = ((const uint4*)WLp)[0]; gB[3] = ((const uint4*)WLp)[1];
    }

    auto storeStage = [&](int s) {
        const float* vf = (const float*)fA;
        uint4 hi[2], lo[2];
        uint32_t* hw = (uint32_t*)hi;
        uint32_t* lw = (uint32_t*)lo;
        #pragma unroll
        for (int q = 0; q < 8; ++q) {
            uint32_t hp[2], lp[2];
            #pragma unroll
            for (int e = 0; e < 2; ++e) {
                float w = vf[2 * q + e] * 64.0f;
                __half h = __float2half_rn(w);
                float r = w - __half2float(h);
                __half l = __float2half_rn(r);
                hp[e] = __half_as_ushort(h);
                lp[e] = __half_as_ushort(l);
            }
            hw[q] = hp[0] | (hp[1] << 16);
            lw[q] = lp[0] | (lp[1] << 16);
        }
        char* aH = smem + SM_AHI + s * A_STG + aoff;
        char* aL = smem + SM_ALO + s * A_STG + aoff;
        *(uint4*)(aH)      = hi[0];
        *(uint4*)(aH + 16) = hi[1];
        *(uint4*)(aL)      = lo[0];
        *(uint4*)(aL + 16) = lo[1];
        char* bH = smem + SM_BHI + s * B_STG + boff;
        char* bL = smem + SM_BLO + s * B_STG + boff;
        *(uint4*)(bH)      = gB[0];
        *(uint4*)(bH + 16) = gB[1];
        *(uint4*)(bL)      = gB[2];
        *(uint4*)(bL + 16) = gB[3];
    };

    storeStage(0);
    __syncthreads();

    for (int kt = 0; kt < NSTG; ++kt) {
        const int cur = kt & 1;

        if (kt + 1 < NSTG) {
            const float4* p = (const float4*)(Ap + (kt + 1) * BK);
            fA[0] = p[0]; fA[1] = p[1]; fA[2] = p[2]; fA[3] = p[3];
            const __half* ph = WHp + (size_t)(kt + 1) * BK * DQv;
            const __half* pl = WLp + (size_t)(kt + 1) * BK * DQv;
            gB[0] = ((const uint4*)ph)[0]; gB[1] = ((const uint4*)ph)[1];
            gB[2] = ((const uint4*)pl)[0]; gB[3] = ((const uint4*)pl)[1];
        }

        #pragma unroll
        for (int kk = 0; kk < 2; ++kk) {
            uint32_t ah[2][4], al[2][4];
            #pragma unroll
            for (int mt = 0; mt < 2; ++mt) {
                uint32_t off = arow_l + (uint32_t)((mt * 16 * A_PAD + kk * 16) * 2);
                LDSM4(ah[mt], aHiB + cur * A_STG + off);
                LDSM4(al[mt], aLoB + cur * A_STG + off);
            }
            #pragma unroll
            for (int np = 0; np < 4; ++np) {
                uint32_t off = brow_l + (uint32_t)((kk * 16 * B_PAD + np * 16) * 2);
                uint32_t bh[4], bl[4];
                LDSM4T(bh, bHiB + cur * B_STG + off);
                LDSM4T(bl, bLoB + cur * B_STG + off);
                #pragma unroll
                for (int mt = 0; mt < 2; ++mt) {
                    #pragma unroll
                    for (int st = 0; st < 2; ++st) {
                        float* c = acc[mt][np * 2 + st];
                        MMA16816(c, ah[mt], bh[2 * st], bh[2 * st + 1]);
                        MMA16816(c, ah[mt], bl[2 * st], bl[2 * st + 1]);
                        MMA16816(c, al[mt], bh[2 * st], bh[2 * st + 1]);
                    }
                }
            }
        }

        if (kt + 1 < NSTG) storeStage((kt + 1) & 1);
        __syncthreads();
    }

    const float inv = 1.0f / 32768.0f;
    float p[4][8];
    #pragma unroll
    for (int r = 0; r < 4; ++r)
        #pragma unroll
        for (int m = 0; m < MI; ++m) p[r][m] = 0.f;

    #pragma unroll
    for (int mt = 0; mt < 2; ++mt) {
        #pragma unroll
        for (int nt = 0; nt < 8; ++nt) {
            #pragma unroll
            for (int i = 0; i < 4; ++i) {
                const int col = wn * 64 + nt * 8 + (lane & 3) * 2 + (i & 1);
                float v = acc[mt][nt][i] * inv + bnS[col];
                float g = 0.5f * v * (1.0f + erff(v * 0.70710678118654752f));
                const int r = mt * 2 + (i >> 1);
                #pragma unroll
                for (int m = 0; m < MI; ++m)
                    p[r][m] = fmaf(g, UsS[m * BN + col], p[r][m]);
            }
        }
    }

    #pragma unroll
    for (int off = 1; off <= 2; off <<= 1)
        #pragma unroll
        for (int r = 0; r < 4; ++r)
            #pragma unroll
            for (int m = 0; m < MI; ++m)
                p[r][m] += __shfl_xor_sync(0xffffffffu, p[r][m], off);

    float* ps = (float*)(smem + SM_AHI);   // [2][128][8]
    if ((lane & 3) == 0) {
        #pragma unroll
        for (int r = 0; r < 4; ++r) {
            const int row = wm * 32 + (r >> 1) * 16 + (lane >> 2) + (r & 1) * 8;
            #pragma unroll
            for (int m = 0; m < MI; ++m)
                ps[(wn * 128 + row) * MI + m] = p[r][m];
        }
    }
    __syncthreads();

    for (int e = tid; e < BM * MI; e += 256) {
        const int row = e >> 3, m = e & 7;
        const int node = (rowBase & (NPG - 1)) + row;
        gs[(b * MI + m) * NPG + node] = ps[row * MI + m] + ps[(128 + row) * MI + m];
    }
}

// ---------------------------------------------------------------------------
// FFMA kernel (round-3 design): 64 rows x full 256 cols, exact fp32 f32x2.
// Rows [HROWS, NTOT). Own register budget: 100 regs.
// ---------------------------------------------------------------------------
__global__ void __maxnreg__(100)
gemm_ffma(const float* __restrict__ x, const float* __restrict__ u,
          const float* __restrict__ Wn, const float* __restrict__ bn)
{
    __shared__ float As2[2][FBK][2 * FBM];   // 8 KB
    __shared__ float Bs[2][FBK][DQv];        // 16 KB
    __shared__ float Us[MI][DQv];            // 8 KB

    const int tid      = threadIdx.x;
    const int rowBase  = HROWS + blockIdx.x * FBM;
    const int b        = rowBase >> 12;
    const int nodeBase = rowBase & (NPG - 1);

    for (int i = tid; i < MI * DQv; i += 256) {
        int m = i >> 8, c = i & 255;
        Us[m][c] = u[(m * NB + b) * DQv + c];
    }

    const int warp = tid >> 5, lane = tid & 31;
    const int r0  = warp * 8;
    const int c0a = lane * 4;

    const int arow  = tid >> 2;
    const int acol2 = (tid & 3) << 1;
    const float* Ap = x + (size_t)(rowBase + arow) * DN + acol2;

    const int bkr = tid >> 6;
    const int bc  = (tid & 63) << 2;

    unsigned long long acc[8][4];
    #pragma unroll
    for (int r = 0; r < 8; ++r)
        #pragma unroll
        for (int c = 0; c < 4; ++c) acc[r][c] = 0ULL;

    {
        float2 av = *(const float2*)(Ap);
        const float* W0 = Wn + (size_t)bkr * DQv + bc;
        float4 bv0 = *(const float4*)(W0);
        float4 bv1 = *(const float4*)(W0 + 4 * DQv);
        As2[0][acol2 + 0][2 * arow] = av.x; As2[0][acol2 + 0][2 * arow + 1] = av.x;
        As2[0][acol2 + 1][2 * arow] = av.y; As2[0][acol2 + 1][2 * arow + 1] = av.y;
        *(float4*)&Bs[0][bkr][bc]     = bv0;
        *(float4*)&Bs[0][bkr + 4][bc] = bv1;
    }
    __syncthreads();

    for (int kt = 0; kt < FNKT; ++kt) {
        const int cur = kt & 1;

        float2 av; float4 bv0, bv1;
        if (kt + 1 < FNKT) {
            av = *(const float2*)(Ap + (kt + 1) * FBK);
            const float* W0 = Wn + (size_t)((kt + 1) * FBK + bkr) * DQv + bc;
            bv0 = *(const float4*)(W0);
            bv1 = *(const float4*)(W0 + 4 * DQv);
        }

        #pragma unroll
        for (int k = 0; k < FBK; ++k) {
            ulonglong2 t0 = *(const ulonglong2*)&Bs[cur][k][c0a];
            ulonglong2 t1 = *(const ulonglong2*)&Bs[cur][k][128 + c0a];
            unsigned long long b2[4] = {t0.x, t0.y, t1.x, t1.y};
            #pragma unroll
            for (int rp = 0; rp < 4; ++rp) {
                ulonglong2 ap = *(const ulonglong2*)&As2[cur][k][2 * (r0 + 2 * rp)];
                #pragma unroll
                for (int half = 0; half < 2; ++half) {
                    const unsigned long long a2 = half ? ap.y : ap.x;
                    const int r = 2 * rp + half;
                    acc[r][0] = fma2(a2, b2[0], acc[r][0]);
                    acc[r][1] = fma2(a2, b2[1], acc[r][1]);
                    acc[r][2] = fma2(a2, b2[2], acc[r][2]);
                    acc[r][3] = fma2(a2, b2[3], acc[r][3]);
                }
            }
        }

        if (kt + 1 < FNKT) {
            const int nxt = cur ^ 1;
            As2[nxt][acol2 + 0][2 * arow] = av.x; As2[nxt][acol2 + 0][2 * arow + 1] = av.x;
            As2[nxt][acol2 + 1][2 * arow] = av.y; As2[nxt][acol2 + 1][2 * arow + 1] = av.y;
            *(float4*)&Bs[nxt][bkr][bc]     = bv0;
            *(float4*)&Bs[nxt][bkr + 4][bc] = bv1;
        }
        __syncthreads();
    }

    float bnv[8];
    *(float4*)&bnv[0] = *(const float4*)(bn + c0a);
    *(float4*)&bnv[4] = *(const float4*)(bn + 128 + c0a);

    #pragma unroll
    for (int r = 0; r < 8; ++r) {
        float h[8];
        #pragma unroll
        for (int c2 = 0; c2 < 4; ++c2) {
            h[2 * c2]     = __uint_as_float((unsigned int)(acc[r][c2]));
            h[2 * c2 + 1] = __uint_as_float((unsigned int)(acc[r][c2] >> 32));
        }
        #pragma unroll
        for (int c = 0; c < 8; ++c) {
            float v = h[c] + bnv[c];
            h[c] = 0.5f * v * (1.0f + erff(v * 0.70710678118654752f));
        }
        const int node = nodeBase + r0 + r;
        #pragma unroll
        for (int m = 0; m < MI; ++m) {
            float p = 0.f;
            #pragma unroll
            for (int c = 0; c < 4; ++c) p = fmaf(h[c], Us[m][c0a + c], p);
            #pragma unroll
            for (int c = 0; c < 4; ++c) p = fmaf(h[4 + c], Us[m][128 + c0a + c], p);
            #pragma unroll
            for (int off = 16; off > 0; off >>= 1)
                p += __shfl_down_sync(0xffffffffu, p, off);
            if (lane == 0) {
                g_s0[(b * MI + m) * NPG + node] = p;
                g_s1[(b * MI + m) * NPG + node] = 0.f;
            }
        }
    }
}

// ---------------------------------------------------------------------------
// Kernel 2: per graph — softmax, gate, exact top-K threshold, mask.
// ---------------------------------------------------------------------------
__global__ void __launch_bounds__(512)
gate_topk(float* __restrict__ out)
{
    __shared__ float gate[NPG];
    __shared__ float buf[NPG];
    __shared__ float red_a[16];
    __shared__ float red_b[16];

    const int b = blockIdx.x;
    const int tid = threadIdx.x;
    const int lane = tid & 31, wid = tid >> 5;

    for (int i = tid; i < NPG; i += 512) gate[i] = 0.f;

    for (int m = 0; m < MI; ++m) {
        const float* s0 = g_s0 + (b * MI + m) * NPG;
        const float* s1 = g_s1 + (b * MI + m) * NPG;
        float v[8];
        float mx = -3.4e38f;
        #pragma unroll
        for (int i = 0; i < 8; ++i) {
            v[i] = s0[(i << 9) + tid] + s1[(i << 9) + tid];
            mx = fmaxf(mx, v[i]);
        }
        #pragma unroll
        for (int off = 16; off > 0; off >>= 1)
            mx = fmaxf(mx, __shfl_xor_sync(0xffffffffu, mx, off));
        if (lane == 0) red_a[wid] = mx;
        __syncthreads();
        mx = red_a[0];
        #pragma unroll
        for (int i = 1; i < 16; ++i) mx = fmaxf(mx, red_a[i]);

        float e[8], se = 0.f;
        #pragma unroll
        for (int i = 0; i < 8; ++i) { e[i] = expf(v[i] - mx); se += e[i]; }
        #pragma unroll
        for (int off = 16; off > 0; off >>= 1)
            se += __shfl_xor_sync(0xffffffffu, se, off);
        if (lane == 0) red_b[wid] = se;
        __syncthreads();
        float tot = 0.f;
        #pragma unroll
        for (int i = 0; i < 16; ++i) tot += red_b[i];

        #pragma unroll
        for (int i = 0; i < 8; ++i) gate[(i << 9) + tid] += e[i] / tot;
        __syncthreads();
    }

    for (int i = tid; i < NPG; i += 512) buf[i] = gate[i];
    __syncthreads();

    for (int k = 2; k <= NPG; k <<= 1) {
        for (int j = k >> 1; j > 0; j >>= 1) {
            for (int i = tid; i < NPG; i += 512) {
                int l = i ^ j;
                if (l > i) {
                    float a0 = buf[i], a1 = buf[l];
                    if (((i & k) == 0) == (a0 > a1)) { buf[i] = a1; buf[l] = a0; }
                }
            }
            __syncthreads();
        }
    }

    const float kth = buf[NPG - KSEL];
    float* o = out + b * NPG;
    for (int i = tid; i < NPG; i += 512)
        o[i] = (gate[i] >= kth) ? 1.0f : 0.0f;
}

// ---------------------------------------------------------------------------
// Host side: fork/join two streams inside graph capture so the HMMA and FFMA
// kernels run CONCURRENTLY (separate register budgets -> true co-residency).
// Stream/events created in a static initializer (no device-memory alloc).
// ---------------------------------------------------------------------------
struct HybridStreams {
    cudaStream_t s2;
    cudaEvent_t evA, evB;
    HybridStreams() {
        cudaStreamCreateWithFlags(&s2, cudaStreamNonBlocking);
        cudaEventCreateWithFlags(&evA, cudaEventDisableTiming);
        cudaEventCreateWithFlags(&evB, cudaEventDisableTiming);
        cudaFuncSetAttribute(gemm_hmma,
                             cudaFuncAttributeMaxDynamicSharedMemorySize, SM_DYN);
    }
};
static HybridStreams g_hs;

extern "C" void kernel_launch(void* const* d_in, const int* in_sizes, int n_in,
                              void* d_out, int out_size) {
    const float* x  = (const float*)d_in[0];
    const float* u  = (const float*)d_in[1];
    const float* Wn = (const float*)d_in[2];
    const float* bn = (const float*)d_in[3];
    // d_in[4] = batch (equal sorted segments -> implicit), d_in[5] = edge_index (unused)

    cudaFuncSetAttribute(gemm_hmma,
                         cudaFuncAttributeMaxDynamicSharedMemorySize, SM_DYN);

    // fork: FFMA kernel on side stream, HMMA (+its W-split prologue) on main
    cudaEventRecord(g_hs.evA, 0);
    cudaStreamWaitEvent(g_hs.s2, g_hs.evA, 0);

    gemm_ffma<<<FBLKS, 256, 0, g_hs.s2>>>(x, u, Wn, bn);

    convert_w<<<DN * DQv / 256, 256>>>(Wn);
    dim3 hgrid(HSLABS, 2);
    gemm_hmma<<<hgrid, 256, SM_DYN>>>(x, u, bn);

    // join
    cudaEventRecord(g_hs.evB, g_hs.s2);
    cudaStreamWaitEvent(0, g_hs.evB, 0);

    gate_topk<<<NB, 512>>>((float*)d_out);
}

// round 9
// speedup vs baseline: 1.1308x; 1.1308x over previous
#include <cuda_runtime.h>
#include <cuda_fp16.h>
#include <math.h>
#include <stdint.h>

#define DN    512
#define DQv   256
#define NPG   4096
#define NB    64
#define MI    8
#define NTOT  (NB*NPG)
#define KSEL  1229           // ceil(0.3 * 4096)

// ---- HMMA tiles
#define BM   128
#define BN   128
#define BK   32
#define NSTG (DN/BK)         // 16

// ---- FFMA tiles (128-thread blocks)
#define FBM  32
#define FBK  8
#define FNKT (DN/FBK)        // 64

// ---- split: H covers rows [0, HROWS), F the rest
#define HSLABS 1548
#define HROWS  (HSLABS*128)            // 198144
#define FBLKS  ((NTOT-HROWS)/FBM)      // 2000

// ---------------- scratch ----------------
__device__ float g_s0[NB * MI * NPG];     // scores partial (H col-half 0 / F full)
__device__ float g_s1[NB * MI * NPG];     // H col-half 1 (F rows: zero)
__device__ __half g_Whi[DN * DQv];        // W*512 split hi
__device__ __half g_Wlo[DN * DQv];        // W*512 split lo

// ---------------- HMMA smem layout (bytes) ----------------
#define A_PAD 40
#define B_PAD 136
#define SM_AHI 0
#define SM_ALO 20480
#define SM_BHI 40960
#define SM_BLO 58368
#define SM_US  75776
#define SM_BNv 79872
#define SM_DYN 80384
#define A_STG  10240
#define B_STG  8704

__device__ __forceinline__ uint32_t smem_u32(const void* p) {
    uint32_t a;
    asm("{ .reg .u64 t; cvta.to.shared.u64 t, %1; cvt.u32.u64 %0, t; }"
        : "=r"(a) : "l"(p));
    return a;
}

#define LDSM4(r, addr) \
    asm volatile("ldmatrix.sync.aligned.m8n8.x4.shared.b16 {%0,%1,%2,%3}, [%4];" \
        : "=r"((r)[0]), "=r"((r)[1]), "=r"((r)[2]), "=r"((r)[3]) : "r"(addr))

#define LDSM4T(r, addr) \
    asm volatile("ldmatrix.sync.aligned.m8n8.x4.trans.shared.b16 {%0,%1,%2,%3}, [%4];" \
        : "=r"((r)[0]), "=r"((r)[1]), "=r"((r)[2]), "=r"((r)[3]) : "r"(addr))

#define MMA16816(c, a, b0, b1) \
    asm volatile("mma.sync.aligned.m16n8k16.row.col.f32.f16.f16.f32 " \
        "{%0,%1,%2,%3}, {%4,%5,%6,%7}, {%8,%9}, {%0,%1,%2,%3};" \
        : "+f"((c)[0]), "+f"((c)[1]), "+f"((c)[2]), "+f"((c)[3]) \
        : "r"((a)[0]), "r"((a)[1]), "r"((a)[2]), "r"((a)[3]), "r"(b0), "r"(b1))

__device__ __forceinline__ unsigned long long fma2(unsigned long long a,
                                                   unsigned long long b,
                                                   unsigned long long c) {
    unsigned long long d;
    asm("fma.rn.f32x2 %0, %1, %2, %3;" : "=l"(d) : "l"(a), "l"(b), "l"(c));
    return d;
}

// ---------------------------------------------------------------------------
// Prologue: W [512][256] fp32 -> fp16 Dekker split of W*512
// ---------------------------------------------------------------------------
__global__ void convert_w(const float* __restrict__ Wn) {
    int idx = blockIdx.x * 256 + threadIdx.x;
    float w = Wn[idx] * 512.0f;
    __half hi = __float2half_rn(w);
    __half lo = __float2half_rn(w - __half2float(hi));
    g_Whi[idx] = hi;
    g_Wlo[idx] = lo;
}

// ---------------------------------------------------------------------------
// HMMA kernel (round-5 design, UNCAPPED registers): 128 x 128, fp16 2-split,
// 3-term, fp32 accum. grid = (HSLABS, 2).
// ---------------------------------------------------------------------------
__global__ void __launch_bounds__(256)
gemm_hmma(const float* __restrict__ x, const float* __restrict__ u,
          const float* __restrict__ bn)
{
    extern __shared__ char smem[];
    const uint32_t sb = smem_u32(smem);
    const int tid  = threadIdx.x;
    const int wid  = tid >> 5, lane = tid & 31;
    const int wm   = wid & 3, wn = wid >> 2;
    const int rowBase = blockIdx.x * BM;
    const int colBase = blockIdx.y * BN;
    const int b = rowBase >> 12;
    float* gs = blockIdx.y ? g_s1 : g_s0;

    float* UsS = (float*)(smem + SM_US);
    float* bnS = (float*)(smem + SM_BNv);
    for (int i = tid; i < MI * BN; i += 256) {
        int m = i >> 7, c = i & 127;
        UsS[i] = u[(m * NB + b) * DQv + colBase + c];
    }
    if (tid < BN) bnS[tid] = bn[colBase + tid];

    const int arow = tid >> 1;
    const int ac0  = (tid & 1) * 16;
    const float* Ap = x + (size_t)(rowBase + arow) * DN + ac0;
    const int aoff  = (arow * A_PAD + ac0) * 2;

    const int brow = tid >> 3;
    const int bc0  = (tid & 7) * 16;
    const __half* WHp = g_Whi + (size_t)brow * DQv + colBase + bc0;
    const __half* WLp = g_Wlo + (size_t)brow * DQv + colBase + bc0;
    const int boff  = (brow * B_PAD + bc0) * 2;

    const uint32_t aHiB = sb + SM_AHI, aLoB = sb + SM_ALO;
    const uint32_t bHiB = sb + SM_BHI, bLoB = sb + SM_BLO;
    const uint32_t arow_l = ((wm * 32 + (lane & 15)) * A_PAD + (lane >> 4) * 8) * 2;
    const uint32_t brow_l = ((lane & 15) * B_PAD + wn * 64 + (lane >> 4) * 8) * 2;

    float acc[2][8][4];
    #pragma unroll
    for (int mt = 0; mt < 2; ++mt)
        #pragma unroll
        for (int nt = 0; nt < 8; ++nt)
            #pragma unroll
            for (int i = 0; i < 4; ++i) acc[mt][nt][i] = 0.f;

    float4 fA[4];
    uint4  gB[4];

    {
        const float4* p = (const float4*)Ap;
        fA[0] = p[0]; fA[1] = p[1]; fA[2] = p[2]; fA[3] = p[3];
        gB[0] = ((const uint4*)WHp)[0]; gB[1] = ((const uint4*)WHp)[1];
        gB[2] = ((const uint4*)WLp)[0]; gB[3] = ((const uint4*)WLp)[1];
    }

    auto storeStage = [&](int s) {
        const float* vf = (const float*)fA;
        uint4 hi[2], lo[2];
        uint32_t* hw = (uint32_t*)hi;
        uint32_t* lw = (uint32_t*)lo;
        #pragma unroll
        for (int q = 0; q < 8; ++q) {
            uint32_t hp[2], lp[2];
            #pragma unroll
            for (int e = 0; e < 2; ++e) {
                float w = vf[2 * q + e] * 64.0f;
                __half h = __float2half_rn(w);
                float r = w - __half2float(h);
                __half l = __float2half_rn(r);
                hp[e] = __half_as_ushort(h);
                lp[e] = __half_as_ushort(l);
            }
            hw[q] = hp[0] | (hp[1] << 16);
            lw[q] = lp[0] | (lp[1] << 16);
        }
        char* aH = smem + SM_AHI + s * A_STG + aoff;
        char* aL = smem + SM_ALO + s * A_STG + aoff;
        *(uint4*)(aH)      = hi[0];
        *(uint4*)(aH + 16) = hi[1];
        *(uint4*)(aL)      = lo[0];
        *(uint4*)(aL + 16) = lo[1];
        char* bH = smem + SM_BHI + s * B_STG + boff;
        char* bL = smem + SM_BLO + s * B_STG + boff;
        *(uint4*)(bH)      = gB[0];
        *(uint4*)(bH + 16) = gB[1];
        *(uint4*)(bL)      = gB[2];
        *(uint4*)(bL + 16) = gB[3];
    };

    storeStage(0);
    __syncthreads();

    for (int kt = 0; kt < NSTG; ++kt) {
        const int cur = kt & 1;

        if (kt + 1 < NSTG) {
            const float4* p = (const float4*)(Ap + (kt + 1) * BK);
            fA[0] = p[0]; fA[1] = p[1]; fA[2] = p[2]; fA[3] = p[3];
            const __half* ph = WHp + (size_t)(kt + 1) * BK * DQv;
            const __half* pl = WLp + (size_t)(kt + 1) * BK * DQv;
            gB[0] = ((const uint4*)ph)[0]; gB[1] = ((const uint4*)ph)[1];
            gB[2] = ((const uint4*)pl)[0]; gB[3] = ((const uint4*)pl)[1];
        }

        #pragma unroll
        for (int kk = 0; kk < 2; ++kk) {
            uint32_t ah[2][4], al[2][4];
            #pragma unroll
            for (int mt = 0; mt < 2; ++mt) {
                uint32_t off = arow_l + (uint32_t)((mt * 16 * A_PAD + kk * 16) * 2);
                LDSM4(ah[mt], aHiB + cur * A_STG + off);
                LDSM4(al[mt], aLoB + cur * A_STG + off);
            }
            #pragma unroll
            for (int np = 0; np < 4; ++np) {
                uint32_t off = brow_l + (uint32_t)((kk * 16 * B_PAD + np * 16) * 2);
                uint32_t bh[4], bl[4];
                LDSM4T(bh, bHiB + cur * B_STG + off);
                LDSM4T(bl, bLoB + cur * B_STG + off);
                #pragma unroll
                for (int mt = 0; mt < 2; ++mt) {
                    #pragma unroll
                    for (int st = 0; st < 2; ++st) {
                        float* c = acc[mt][np * 2 + st];
                        MMA16816(c, ah[mt], bh[2 * st], bh[2 * st + 1]);
                        MMA16816(c, ah[mt], bl[2 * st], bl[2 * st + 1]);
                        MMA16816(c, al[mt], bh[2 * st], bh[2 * st + 1]);
                    }
                }
            }
        }

        if (kt + 1 < NSTG) storeStage((kt + 1) & 1);
        __syncthreads();
    }

    const float inv = 1.0f / 32768.0f;
    float p[4][8];
    #pragma unroll
    for (int r = 0; r < 4; ++r)
        #pragma unroll
        for (int m = 0; m < MI; ++m) p[r][m] = 0.f;

    #pragma unroll
    for (int mt = 0; mt < 2; ++mt) {
        #pragma unroll
        for (int nt = 0; nt < 8; ++nt) {
            #pragma unroll
            for (int i = 0; i < 4; ++i) {
                const int col = wn * 64 + nt * 8 + (lane & 3) * 2 + (i & 1);
                float v = acc[mt][nt][i] * inv + bnS[col];
                float g = 0.5f * v * (1.0f + erff(v * 0.70710678118654752f));
                const int r = mt * 2 + (i >> 1);
                #pragma unroll
                for (int m = 0; m < MI; ++m)
                    p[r][m] = fmaf(g, UsS[m * BN + col], p[r][m]);
            }
        }
    }

    #pragma unroll
    for (int off = 1; off <= 2; off <<= 1)
        #pragma unroll
        for (int r = 0; r < 4; ++r)
            #pragma unroll
            for (int m = 0; m < MI; ++m)
                p[r][m] += __shfl_xor_sync(0xffffffffu, p[r][m], off);

    float* ps = (float*)(smem + SM_AHI);   // [2][128][8]
    if ((lane & 3) == 0) {
        #pragma unroll
        for (int r = 0; r < 4; ++r) {
            const int row = wm * 32 + (r >> 1) * 16 + (lane >> 2) + (r & 1) * 8;
            #pragma unroll
            for (int m = 0; m < MI; ++m)
                ps[(wn * 128 + row) * MI + m] = p[r][m];
        }
    }
    __syncthreads();

    for (int e = tid; e < BM * MI; e += 256) {
        const int row = e >> 3, m = e & 7;
        const int node = (rowBase & (NPG - 1)) + row;
        gs[(b * MI + m) * NPG + node] = ps[row * MI + m] + ps[(128 + row) * MI + m];
    }
}

// ---------------------------------------------------------------------------
// FFMA kernel: 128 threads, 32 rows x full 256 cols, exact fp32 f32x2.
// Rows [HROWS, NTOT). Small footprint (maxnreg 104, 28KB smem) so one F CTA
// co-resides with one H CTA per SM and feeds the idle fma pipe.
// ---------------------------------------------------------------------------
__global__ void __maxnreg__(104)
gemm_ffma(const float* __restrict__ x, const float* __restrict__ u,
          const float* __restrict__ Wn, const float* __restrict__ bn)
{
    __shared__ float As2[2][FBK][2 * FBM];   // 4 KB
    __shared__ float Bs[2][FBK][DQv];        // 16 KB
    __shared__ float Us[MI][DQv];            // 8 KB

    const int tid      = threadIdx.x;          // 0..127
    const int rowBase  = HROWS + blockIdx.x * FBM;
    const int b        = rowBase >> 12;
    const int nodeBase = rowBase & (NPG - 1);

    for (int i = tid; i < MI * DQv; i += 128) {
        int m = i >> 8, c = i & 255;
        Us[m][c] = u[(m * NB + b) * DQv + c];
    }

    const int warp = tid >> 5, lane = tid & 31;
    const int r0  = warp * 8;            // 4 warps x 8 rows = 32 rows
    const int c0a = lane * 4;            // cols c0a..+3 and 128+c0a..+3

    // A loader: 32 rows x 8 k = 256 els / 128 thr = 2 els (consecutive k)
    const int arow  = tid >> 2;          // 0..31
    const int acol2 = (tid & 3) << 1;
    const float* Ap = x + (size_t)(rowBase + arow) * DN + acol2;

    // B loader: 8 k-rows x 256 cols = 2048 els / 128 thr = 16 els = 4 float4
    const int bkr = tid >> 5;            // 0..3 -> rows {bkr, bkr+4}
    const int bc  = (lane) << 3;         // 0..248, 8 cols per thread

    unsigned long long acc[8][4];
    #pragma unroll
    for (int r = 0; r < 8; ++r)
        #pragma unroll
        for (int c = 0; c < 4; ++c) acc[r][c] = 0ULL;

    {
        float2 av = *(const float2*)(Ap);
        const float* W0 = Wn + (size_t)bkr * DQv + bc;
        float4 b00 = *(const float4*)(W0);
        float4 b01 = *(const float4*)(W0 + 4);
        float4 b10 = *(const float4*)(W0 + 4 * DQv);
        float4 b11 = *(const float4*)(W0 + 4 * DQv + 4);
        As2[0][acol2 + 0][2 * arow] = av.x; As2[0][acol2 + 0][2 * arow + 1] = av.x;
        As2[0][acol2 + 1][2 * arow] = av.y; As2[0][acol2 + 1][2 * arow + 1] = av.y;
        *(float4*)&Bs[0][bkr][bc]         = b00;
        *(float4*)&Bs[0][bkr][bc + 4]     = b01;
        *(float4*)&Bs[0][bkr + 4][bc]     = b10;
        *(float4*)&Bs[0][bkr + 4][bc + 4] = b11;
    }
    __syncthreads();

    for (int kt = 0; kt < FNKT; ++kt) {
        const int cur = kt & 1;

        float2 av; float4 b00, b01, b10, b11;
        if (kt + 1 < FNKT) {
            av = *(const float2*)(Ap + (kt + 1) * FBK);
            const float* W0 = Wn + (size_t)((kt + 1) * FBK + bkr) * DQv + bc;
            b00 = *(const float4*)(W0);
            b01 = *(const float4*)(W0 + 4);
            b10 = *(const float4*)(W0 + 4 * DQv);
            b11 = *(const float4*)(W0 + 4 * DQv + 4);
        }

        #pragma unroll
        for (int k = 0; k < FBK; ++k) {
            ulonglong2 t0 = *(const ulonglong2*)&Bs[cur][k][c0a];
            ulonglong2 t1 = *(const ulonglong2*)&Bs[cur][k][128 + c0a];
            unsigned long long b2[4] = {t0.x, t0.y, t1.x, t1.y};
            #pragma unroll
            for (int rp = 0; rp < 4; ++rp) {
                ulonglong2 ap = *(const ulonglong2*)&As2[cur][k][2 * (r0 + 2 * rp)];
                #pragma unroll
                for (int half = 0; half < 2; ++half) {
                    const unsigned long long a2 = half ? ap.y : ap.x;
                    const int r = 2 * rp + half;
                    acc[r][0] = fma2(a2, b2[0], acc[r][0]);
                    acc[r][1] = fma2(a2, b2[1], acc[r][1]);
                    acc[r][2] = fma2(a2, b2[2], acc[r][2]);
                    acc[r][3] = fma2(a2, b2[3], acc[r][3]);
                }
            }
        }

        if (kt + 1 < FNKT) {
            const int nxt = cur ^ 1;
            As2[nxt][acol2 + 0][2 * arow] = av.x; As2[nxt][acol2 + 0][2 * arow + 1] = av.x;
            As2[nxt][acol2 + 1][2 * arow] = av.y; As2[nxt][acol2 + 1][2 * arow + 1] = av.y;
            *(float4*)&Bs[nxt][bkr][bc]         = b00;
            *(float4*)&Bs[nxt][bkr][bc + 4]     = b01;
            *(float4*)&Bs[nxt][bkr + 4][bc]     = b10;
            *(float4*)&Bs[nxt][bkr + 4][bc + 4] = b11;
        }
        __syncthreads();
    }

    float bnv[8];
    *(float4*)&bnv[0] = *(const float4*)(bn + c0a);
    *(float4*)&bnv[4] = *(const float4*)(bn + 128 + c0a);

    #pragma unroll
    for (int r = 0; r < 8; ++r) {
        float h[8];
        #pragma unroll
        for (int c2 = 0; c2 < 4; ++c2) {
            h[2 * c2]     = __uint_as_float((unsigned int)(acc[r][c2]));
            h[2 * c2 + 1] = __uint_as_float((unsigned int)(acc[r][c2] >> 32));
        }
        #pragma unroll
        for (int c = 0; c < 8; ++c) {
            float v = h[c] + bnv[c];
            h[c] = 0.5f * v * (1.0f + erff(v * 0.70710678118654752f));
        }
        const int node = nodeBase + r0 + r;
        #pragma unroll
        for (int m = 0; m < MI; ++m) {
            float p = 0.f;
            #pragma unroll
            for (int c = 0; c < 4; ++c) p = fmaf(h[c], Us[m][c0a + c], p);
            #pragma unroll
            for (int c = 0; c < 4; ++c) p = fmaf(h[4 + c], Us[m][128 + c0a + c], p);
            #pragma unroll
            for (int off = 16; off > 0; off >>= 1)
                p += __shfl_down_sync(0xffffffffu, p, off);
            if (lane == 0) {
                g_s0[(b * MI + m) * NPG + node] = p;
                g_s1[(b * MI + m) * NPG + node] = 0.f;
            }
        }
    }
}

// ---------------------------------------------------------------------------
// Kernel 2: per graph — softmax, gate, exact top-K threshold, mask.
// ---------------------------------------------------------------------------
__global__ void __launch_bounds__(512)
gate_topk(float* __restrict__ out)
{
    __shared__ float gate[NPG];
    __shared__ float buf[NPG];
    __shared__ float red_a[16];
    __shared__ float red_b[16];

    const int b = blockIdx.x;
    const int tid = threadIdx.x;
    const int lane = tid & 31, wid = tid >> 5;

    for (int i = tid; i < NPG; i += 512) gate[i] = 0.f;

    for (int m = 0; m < MI; ++m) {
        const float* s0 = g_s0 + (b * MI + m) * NPG;
        const float* s1 = g_s1 + (b * MI + m) * NPG;
        float v[8];
        float mx = -3.4e38f;
        #pragma unroll
        for (int i = 0; i < 8; ++i) {
            v[i] = s0[(i << 9) + tid] + s1[(i << 9) + tid];
            mx = fmaxf(mx, v[i]);
        }
        #pragma unroll
        for (int off = 16; off > 0; off >>= 1)
            mx = fmaxf(mx, __shfl_xor_sync(0xffffffffu, mx, off));
        if (lane == 0) red_a[wid] = mx;
        __syncthreads();
        mx = red_a[0];
        #pragma unroll
        for (int i = 1; i < 16; ++i) mx = fmaxf(mx, red_a[i]);

        float e[8], se = 0.f;
        #pragma unroll
        for (int i = 0; i < 8; ++i) { e[i] = expf(v[i] - mx); se += e[i]; }
        #pragma unroll
        for (int off = 16; off > 0; off >>= 1)
            se += __shfl_xor_sync(0xffffffffu, se, off);
        if (lane == 0) red_b[wid] = se;
        __syncthreads();
        float tot = 0.f;
        #pragma unroll
        for (int i = 0; i < 16; ++i) tot += red_b[i];

        #pragma unroll
        for (int i = 0; i < 8; ++i) gate[(i << 9) + tid] += e[i] / tot;
        __syncthreads();
    }

    for (int i = tid; i < NPG; i += 512) buf[i] = gate[i];
    __syncthreads();

    for (int k = 2; k <= NPG; k <<= 1) {
        for (int j = k >> 1; j > 0; j >>= 1) {
            for (int i = tid; i < NPG; i += 512) {
                int l = i ^ j;
                if (l > i) {
                    float a0 = buf[i], a1 = buf[l];
                    if (((i & k) == 0) == (a0 > a1)) { buf[i] = a1; buf[l] = a0; }
                }
            }
            __syncthreads();
        }
    }

    const float kth = buf[NPG - KSEL];
    float* o = out + b * NPG;
    for (int i = tid; i < NPG; i += 512)
        o[i] = (gate[i] >= kth) ? 1.0f : 0.0f;
}

// ---------------------------------------------------------------------------
// Host: fork/join two streams inside graph capture. H uncapped (no spills);
// F small (128 thr, 104 regs, 28KB) so it co-resides beside H on every SM.
// ---------------------------------------------------------------------------
struct HybridStreams {
    cudaStream_t s2;
    cudaEvent_t evA, evB;
    HybridStreams() {
        cudaStreamCreateWithFlags(&s2, cudaStreamNonBlocking);
        cudaEventCreateWithFlags(&evA, cudaEventDisableTiming);
        cudaEventCreateWithFlags(&evB, cudaEventDisableTiming);
        cudaFuncSetAttribute(gemm_hmma,
                             cudaFuncAttributeMaxDynamicSharedMemorySize, SM_DYN);
    }
};
static HybridStreams g_hs;

extern "C" void kernel_launch(void* const* d_in, const int* in_sizes, int n_in,
                              void* d_out, int out_size) {
    const float* x  = (const float*)d_in[0];
    const float* u  = (const float*)d_in[1];
    const float* Wn = (const float*)d_in[2];
    const float* bn = (const float*)d_in[3];
    // d_in[4] = batch (equal sorted segments -> implicit), d_in[5] = edge_index (unused)

    cudaFuncSetAttribute(gemm_hmma,
                         cudaFuncAttributeMaxDynamicSharedMemorySize, SM_DYN);

    // fork: FFMA kernel on side stream, HMMA (+its W-split prologue) on main
    cudaEventRecord(g_hs.evA, 0);
    cudaStreamWaitEvent(g_hs.s2, g_hs.evA, 0);

    gemm_ffma<<<FBLKS, 128, 0, g_hs.s2>>>(x, u, Wn, bn);

    convert_w<<<DN * DQv / 256, 256>>>(Wn);
    dim3 hgrid(HSLABS, 2);
    gemm_hmma<<<hgrid, 256, SM_DYN>>>(x, u, bn);

    // join
    cudaEventRecord(g_hs.evB, g_hs.s2);
    cudaStreamWaitEvent(0, g_hs.evB, 0);

    gate_topk<<<NB, 512>>>((float*)d_out);
}

// round 10
// speedup vs baseline: 1.8122x; 1.6025x over previous
#include <cuda_runtime.h>
#include <cuda_fp16.h>
#include <math.h>
#include <stdint.h>

#define DN    512
#define DQv   256
#define NPG   4096
#define NB    64
#define MI    8
#define NTOT  (NB*NPG)
#define KSEL  1229           // ceil(0.3 * 4096)

#define BM   128
#define BN   128
#define BK   32
#define NSTG (DN/BK)         // 16

// ---------------- scratch ----------------
__device__ float g_s0[NB * MI * NPG];     // scores partial, col-half 0 (8 MB)
__device__ float g_s1[NB * MI * NPG];     // col-half 1
__device__ __half g_Whi[DN * DQv];        // W*512 split hi
__device__ __half g_Wlo[DN * DQv];        // W*512 split lo

// ---------------- smem layout (bytes) ----------------
#define A_PAD 40      // halves per A row (32 data + 8 pad)
#define B_PAD 136     // halves per B row (128 data + 8 pad)
#define SM_AHI 0                      // [2][128*40] halves = 20480 B
#define SM_ALO 20480
#define SM_BHI 40960                  // [2][32*136] halves = 17408 B
#define SM_BLO 58368
#define SM_US  75776                  // 8*128 floats = 4096 B
#define SM_BNv 79872                  // 128 floats = 512 B
#define SM_DYN 80384
#define A_STG  10240                  // bytes per A stage
#define B_STG  8704                   // bytes per B stage

__device__ __forceinline__ uint32_t smem_u32(const void* p) {
    uint32_t a;
    asm("{ .reg .u64 t; cvta.to.shared.u64 t, %1; cvt.u32.u64 %0, t; }"
        : "=r"(a) : "l"(p));
    return a;
}

#define LDSM4(r, addr) \
    asm volatile("ldmatrix.sync.aligned.m8n8.x4.shared.b16 {%0,%1,%2,%3}, [%4];" \
        : "=r"((r)[0]), "=r"((r)[1]), "=r"((r)[2]), "=r"((r)[3]) : "r"(addr))

#define LDSM4T(r, addr) \
    asm volatile("ldmatrix.sync.aligned.m8n8.x4.trans.shared.b16 {%0,%1,%2,%3}, [%4];" \
        : "=r"((r)[0]), "=r"((r)[1]), "=r"((r)[2]), "=r"((r)[3]) : "r"(addr))

#define MMA16816(c, a, b0, b1) \
    asm volatile("mma.sync.aligned.m16n8k16.row.col.f32.f16.f16.f32 " \
        "{%0,%1,%2,%3}, {%4,%5,%6,%7}, {%8,%9}, {%0,%1,%2,%3};" \
        : "+f"((c)[0]), "+f"((c)[1]), "+f"((c)[2]), "+f"((c)[3]) \
        : "r"((a)[0]), "r"((a)[1]), "r"((a)[2]), "r"((a)[3]), "r"(b0), "r"(b1))

#define CPASYNC16(dst, src) \
    asm volatile("cp.async.ca.shared.global [%0], [%1], 16;" \
        :: "r"(dst), "l"(src) : "memory")
#define CPASYNC_COMMIT() asm volatile("cp.async.commit_group;" ::: "memory")
#define CPASYNC_WAIT0()  asm volatile("cp.async.wait_group 0;" ::: "memory")

// ---------------------------------------------------------------------------
// Prologue: W [512][256] fp32 -> fp16 Dekker split of W*512 (exact residual)
// ---------------------------------------------------------------------------
__global__ void convert_w(const float* __restrict__ Wn) {
    int idx = blockIdx.x * 256 + threadIdx.x;     // 0..131071
    float w = Wn[idx] * 512.0f;
    __half hi = __float2half_rn(w);
    __half lo = __float2half_rn(w - __half2float(hi));
    g_Whi[idx] = hi;
    g_Wlo[idx] = lo;
}

// ---------------------------------------------------------------------------
// Main: h = gelu((x@Wn)+bn) fused with partial scores over this block's 128
// cols. fp16 2-split, 3-term HMMA, fp32 accum. grid = (2048, 2).
// B tiles stream via cp.async; A converted in registers, double-buffered.
// ---------------------------------------------------------------------------
__global__ void __launch_bounds__(256)
gemm_hmma(const float* __restrict__ x, const float* __restrict__ u,
          const float* __restrict__ bn)
{
    extern __shared__ char smem[];
    const uint32_t sb = smem_u32(smem);
    const int tid  = threadIdx.x;
    const int wid  = tid >> 5, lane = tid & 31;
    const int wm   = wid & 3, wn = wid >> 2;     // warp grid 4(M) x 2(N)
    const int rowBase = blockIdx.x * BM;
    const int colBase = blockIdx.y * BN;
    const int b = rowBase >> 12;
    float* gs = blockIdx.y ? g_s1 : g_s0;

    // stage Us (8 x 128 cols of this half) and bn
    float* UsS = (float*)(smem + SM_US);
    float* bnS = (float*)(smem + SM_BNv);
    for (int i = tid; i < MI * BN; i += 256) {
        int m = i >> 7, c = i & 127;
        UsS[i] = u[(m * NB + b) * DQv + colBase + c];
    }
    if (tid < BN) bnS[tid] = bn[colBase + tid];

    // ---- loaders
    const int arow = tid >> 1;                 // 128 rows, 2 thr/row
    const int ac0  = (tid & 1) * 16;           // 16 k's each
    const float* Ap = x + (size_t)(rowBase + arow) * DN + ac0;
    const int aoff  = (arow * A_PAD + ac0) * 2;

    const int brow = tid >> 3;                 // 32 k-rows, 8 thr/row
    const int bc0  = (tid & 7) * 16;           // 16 cols each
    const __half* WHp = g_Whi + (size_t)brow * DQv + colBase + bc0;
    const __half* WLp = g_Wlo + (size_t)brow * DQv + colBase + bc0;
    const int boff  = (brow * B_PAD + bc0) * 2;

    // ldmatrix per-lane base terms
    const uint32_t aHiB = sb + SM_AHI, aLoB = sb + SM_ALO;
    const uint32_t bHiB = sb + SM_BHI, bLoB = sb + SM_BLO;
    const uint32_t arow_l = ((wm * 32 + (lane & 15)) * A_PAD + (lane >> 4) * 8) * 2;
    const uint32_t brow_l = ((lane & 15) * B_PAD + wn * 64 + (lane >> 4) * 8) * 2;

    float acc[2][8][4];
    #pragma unroll
    for (int mt = 0; mt < 2; ++mt)
        #pragma unroll
        for (int nt = 0; nt < 8; ++nt)
            #pragma unroll
            for (int i = 0; i < 4; ++i) acc[mt][nt][i] = 0.f;

    float4 fA[4];

    auto issueB = [&](int s, int kt) {
        const __half* ph = WHp + (size_t)kt * BK * DQv;
        const __half* pl = WLp + (size_t)kt * BK * DQv;
        uint32_t dH = bHiB + s * B_STG + boff;
        uint32_t dL = bLoB + s * B_STG + boff;
        CPASYNC16(dH,      ph);
        CPASYNC16(dH + 16, ph + 8);
        CPASYNC16(dL,      pl);
        CPASYNC16(dL + 16, pl + 8);
        CPASYNC_COMMIT();
    };

    auto storeA = [&](int s) {
        const float* vf = (const float*)fA;
        uint4 hi[2], lo[2];
        uint32_t* hw = (uint32_t*)hi;
        uint32_t* lw = (uint32_t*)lo;
        #pragma unroll
        for (int q = 0; q < 8; ++q) {
            uint32_t hp[2], lp[2];
            #pragma unroll
            for (int e = 0; e < 2; ++e) {
                float w = vf[2 * q + e] * 64.0f;
                __half h = __float2half_rn(w);
                float r = w - __half2float(h);
                __half l = __float2half_rn(r);
                hp[e] = __half_as_ushort(h);
                lp[e] = __half_as_ushort(l);
            }
            hw[q] = hp[0] | (hp[1] << 16);
            lw[q] = lp[0] | (lp[1] << 16);
        }
        char* aH = smem + SM_AHI + s * A_STG + aoff;
        char* aL = smem + SM_ALO + s * A_STG + aoff;
        *(uint4*)(aH)      = hi[0];
        *(uint4*)(aH + 16) = hi[1];
        *(uint4*)(aL)      = lo[0];
        *(uint4*)(aL + 16) = lo[1];
    };

    // ---- prologue: stage 0
    issueB(0, 0);
    {
        const float4* p = (const float4*)Ap;
        fA[0] = p[0]; fA[1] = p[1]; fA[2] = p[2]; fA[3] = p[3];
    }
    storeA(0);
    CPASYNC_WAIT0();
    __syncthreads();

    for (int kt = 0; kt < NSTG; ++kt) {
        const int cur = kt & 1;

        // kick off next stage's B copies and A register loads BEFORE compute
        if (kt + 1 < NSTG) {
            issueB(cur ^ 1, kt + 1);
            const float4* p = (const float4*)(Ap + (kt + 1) * BK);
            fA[0] = p[0]; fA[1] = p[1]; fA[2] = p[2]; fA[3] = p[3];
        }

        // compute: 2 x k16 steps
        #pragma unroll
        for (int kk = 0; kk < 2; ++kk) {
            uint32_t ah[2][4], al[2][4];
            #pragma unroll
            for (int mt = 0; mt < 2; ++mt) {
                uint32_t off = arow_l + (uint32_t)((mt * 16 * A_PAD + kk * 16) * 2);
                LDSM4(ah[mt], aHiB + cur * A_STG + off);
                LDSM4(al[mt], aLoB + cur * A_STG + off);
            }
            #pragma unroll
            for (int np = 0; np < 4; ++np) {
                uint32_t off = brow_l + (uint32_t)((kk * 16 * B_PAD + np * 16) * 2);
                uint32_t bh[4], bl[4];
                LDSM4T(bh, bHiB + cur * B_STG + off);
                LDSM4T(bl, bLoB + cur * B_STG + off);
                #pragma unroll
                for (int mt = 0; mt < 2; ++mt) {
                    #pragma unroll
                    for (int st = 0; st < 2; ++st) {
                        float* c = acc[mt][np * 2 + st];
                        MMA16816(c, ah[mt], bh[2 * st], bh[2 * st + 1]);
                        MMA16816(c, ah[mt], bl[2 * st], bl[2 * st + 1]);
                        MMA16816(c, al[mt], bh[2 * st], bh[2 * st + 1]);
                    }
                }
            }
        }

        if (kt + 1 < NSTG) storeA(cur ^ 1);
        CPASYNC_WAIT0();
        __syncthreads();
    }

    // ---- epilogue: scale back, bias, exact GELU, partial score dots
    const float inv = 1.0f / 32768.0f;     // undo x*64 * W*512
    float p[4][8];
    #pragma unroll
    for (int r = 0; r < 4; ++r)
        #pragma unroll
        for (int m = 0; m < MI; ++m) p[r][m] = 0.f;

    #pragma unroll
    for (int mt = 0; mt < 2; ++mt) {
        #pragma unroll
        for (int nt = 0; nt < 8; ++nt) {
            #pragma unroll
            for (int i = 0; i < 4; ++i) {
                const int col = wn * 64 + nt * 8 + (lane & 3) * 2 + (i & 1);
                float v = acc[mt][nt][i] * inv + bnS[col];
                float g = 0.5f * v * (1.0f + erff(v * 0.70710678118654752f));
                const int r = mt * 2 + (i >> 1);
                #pragma unroll
                for (int m = 0; m < MI; ++m)
                    p[r][m] = fmaf(g, UsS[m * BN + col], p[r][m]);
            }
        }
    }

    // reduce across the 4 lanes of each quad (cols partition)
    #pragma unroll
    for (int off = 1; off <= 2; off <<= 1)
        #pragma unroll
        for (int r = 0; r < 4; ++r)
            #pragma unroll
            for (int m = 0; m < MI; ++m)
                p[r][m] += __shfl_xor_sync(0xffffffffu, p[r][m], off);

    // combine the two wn halves via smem (reuse A region; all reads done)
    float* ps = (float*)(smem + SM_AHI);   // [2][128][8] floats = 8 KB
    if ((lane & 3) == 0) {
        #pragma unroll
        for (int r = 0; r < 4; ++r) {
            const int row = wm * 32 + (r >> 1) * 16 + (lane >> 2) + (r & 1) * 8;
            #pragma unroll
            for (int m = 0; m < MI; ++m)
                ps[(wn * 128 + row) * MI + m] = p[r][m];
        }
    }
    __syncthreads();

    for (int e = tid; e < BM * MI; e += 256) {
        const int row = e >> 3, m = e & 7;
        const int node = (rowBase & (NPG - 1)) + row;
        gs[(b * MI + m) * NPG + node] = ps[row * MI + m] + ps[(128 + row) * MI + m];
    }
}

// ---------------------------------------------------------------------------
// Kernel 2: per graph — softmax over n per (m), gate = sum_m attn,
//           exact K-th largest via in-smem bitonic sort, mask = gate >= kth.
// 1024 threads: 4 elems/thread -> half the per-step serialization of 512 thr.
// ---------------------------------------------------------------------------
__global__ void __launch_bounds__(1024)
gate_topk(float* __restrict__ out)
{
    __shared__ float gate[NPG];   // 16 KB
    __shared__ float buf[NPG];    // 16 KB
    __shared__ float red_a[32];
    __shared__ float red_b[32];

    const int b = blockIdx.x;
    const int tid = threadIdx.x;
    const int lane = tid & 31, wid = tid >> 5;

    for (int i = tid; i < NPG; i += 1024) gate[i] = 0.f;

    for (int m = 0; m < MI; ++m) {
        const float* s0 = g_s0 + (b * MI + m) * NPG;
        const float* s1 = g_s1 + (b * MI + m) * NPG;
        float v[4];
        float mx = -3.4e38f;
        #pragma unroll
        for (int i = 0; i < 4; ++i) {
            v[i] = s0[(i << 10) + tid] + s1[(i << 10) + tid];
            mx = fmaxf(mx, v[i]);
        }
        #pragma unroll
        for (int off = 16; off > 0; off >>= 1)
            mx = fmaxf(mx, __shfl_xor_sync(0xffffffffu, mx, off));
        if (lane == 0) red_a[wid] = mx;
        __syncthreads();
        mx = red_a[0];
        #pragma unroll
        for (int i = 1; i < 32; ++i) mx = fmaxf(mx, red_a[i]);

        float e[4], se = 0.f;
        #pragma unroll
        for (int i = 0; i < 4; ++i) { e[i] = expf(v[i] - mx); se += e[i]; }
        #pragma unroll
        for (int off = 16; off > 0; off >>= 1)
            se += __shfl_xor_sync(0xffffffffu, se, off);
        if (lane == 0) red_b[wid] = se;
        __syncthreads();
        float tot = 0.f;
        #pragma unroll
        for (int i = 0; i < 32; ++i) tot += red_b[i];

        #pragma unroll
        for (int i = 0; i < 4; ++i)
            gate[(i << 10) + tid] += e[i] / tot;   // per-thread-private slots
        __syncthreads();   // protect red arrays for next m
    }

    for (int i = tid; i < NPG; i += 1024) buf[i] = gate[i];
    __syncthreads();

    // bitonic sort ascending (4096 elements, all finite)
    for (int k = 2; k <= NPG; k <<= 1) {
        for (int j = k >> 1; j > 0; j >>= 1) {
            for (int i = tid; i < NPG; i += 1024) {
                int l = i ^ j;
                if (l > i) {
                    float a0 = buf[i], a1 = buf[l];
                    if (((i & k) == 0) == (a0 > a1)) { buf[i] = a1; buf[l] = a0; }
                }
            }
            __syncthreads();
        }
    }

    const float kth = buf[NPG - KSEL];   // K-th largest
    float* o = out + b * NPG;
    for (int i = tid; i < NPG; i += 1024)
        o[i] = (gate[i] >= kth) ? 1.0f : 0.0f;
}

// ---------------------------------------------------------------------------
extern "C" void kernel_launch(void* const* d_in, const int* in_sizes, int n_in,
                              void* d_out, int out_size) {
    const float* x  = (const float*)d_in[0];
    const float* u  = (const float*)d_in[1];
    const float* Wn = (const float*)d_in[2];
    const float* bn = (const float*)d_in[3];
    // d_in[4] = batch (equal sorted segments -> implicit), d_in[5] = edge_index (unused)

    cudaFuncSetAttribute(gemm_hmma,
                         cudaFuncAttributeMaxDynamicSharedMemorySize, SM_DYN);

    convert_w<<<DN * DQv / 256, 256>>>(Wn);
    dim3 grid(NTOT / BM, 2);
    gemm_hmma<<<grid, 256, SM_DYN>>>(x, u, bn);
    gate_topk<<<NB, 1024>>>((float*)d_out);
}